// round 3
// baseline (speedup 1.0000x reference)
#include <cuda_runtime.h>
#include <cuda_bf16.h>

// ChannelPruner: out[b,o,h,w] = sum_c w[o,c] * x[b,c,h,w]
// x: (32, 256, 56, 56) fp32, w: (256, 256, 1, 1) fp32.
// Generic sparse-row formulation (correct for ANY w): compact nonzeros of
// row w[o,:] once per block, then stream 8 batch-planes with MLP-8 unroll.
// For the pruned-identity weight this degenerates to copy-or-zero.

#define N_CH    256
#define HW4     784          // 56*56/4 float4 per plane
#define NBATCH  32
#define BPG     8            // batches per block
#define NGROUPS (NBATCH / BPG)

__global__ __launch_bounds__(256, 8)
void channel_pruner_kernel(const float4* __restrict__ X,
                           const float4* __restrict__ W,   // row o = W[o*64 .. o*64+63]
                           float4* __restrict__ O)
{
    const int o  = blockIdx.x;          // output channel
    const int b0 = blockIdx.y * BPG;    // first batch of this block's group
    const int tid = threadIdx.x;        // 256 threads

    __shared__ int   s_cnt[64];
    __shared__ int   s_off[64];
    __shared__ int   s_nnz;
    __shared__ int   s_c[N_CH];
    __shared__ float s_v[N_CH];

    // --- Phase 1: cooperative scan of w row o (64 float4 = 256 floats) ---
    float4 w4;
    int myCnt = 0;
    if (tid < 64) {
        w4 = __ldg(&W[o * 64 + tid]);
        myCnt = (w4.x != 0.0f) + (w4.y != 0.0f) + (w4.z != 0.0f) + (w4.w != 0.0f);
        s_cnt[tid] = myCnt;
    }
    __syncthreads();

    // Deterministic serial exclusive scan by thread 0 (64 adds; amortized 8x)
    if (tid == 0) {
        int run = 0;
        #pragma unroll
        for (int i = 0; i < 64; i++) {
            s_off[i] = run;
            run += s_cnt[i];
        }
        s_nnz = run;
    }
    __syncthreads();

    if (tid < 64 && myCnt > 0) {
        int p = s_off[tid];
        int cbase = tid * 4;
        if (w4.x != 0.0f) { s_c[p] = cbase + 0; s_v[p] = w4.x; p++; }
        if (w4.y != 0.0f) { s_c[p] = cbase + 1; s_v[p] = w4.y; p++; }
        if (w4.z != 0.0f) { s_c[p] = cbase + 2; s_v[p] = w4.z; p++; }
        if (w4.w != 0.0f) { s_c[p] = cbase + 3; s_v[p] = w4.w; p++; }
    }
    __syncthreads();

    const int nnz = s_nnz;
    // base pointers for the 8 batches of this group
    const size_t planeStride = (size_t)N_CH * HW4;   // one batch of x / out
    const float4* __restrict__ Xg = X + (size_t)b0 * planeStride;
    float4* __restrict__ Og = O + (size_t)b0 * planeStride + (size_t)o * HW4;

    // --- Phase 2: stream 8 planes. ---
    if (nnz == 0) {
        const float4 z = make_float4(0.f, 0.f, 0.f, 0.f);
        for (int s = tid; s < HW4; s += 256) {
            #pragma unroll
            for (int b = 0; b < BPG; b++)
                __stcs(&Og[(size_t)b * planeStride + s], z);
        }
    } else if (nnz == 1) {
        const float  v = s_v[0];
        const size_t cOff = (size_t)s_c[0] * HW4;
        for (int s = tid; s < HW4; s += 256) {
            float4 a[BPG];
            #pragma unroll
            for (int b = 0; b < BPG; b++)
                a[b] = __ldg(&Xg[(size_t)b * planeStride + cOff + s]);
            #pragma unroll
            for (int b = 0; b < BPG; b++) {
                a[b].x *= v; a[b].y *= v; a[b].z *= v; a[b].w *= v;
                __stcs(&Og[(size_t)b * planeStride + s], a[b]);
            }
        }
    } else {
        // generic sparse accumulation: 4 batches at a time to bound registers
        for (int s = tid; s < HW4; s += 256) {
            #pragma unroll
            for (int bb = 0; bb < BPG; bb += 4) {
                float4 acc0 = make_float4(0.f, 0.f, 0.f, 0.f);
                float4 acc1 = acc0, acc2 = acc0, acc3 = acc0;
                for (int k = 0; k < nnz; k++) {
                    const float  v = s_v[k];
                    const size_t off = (size_t)s_c[k] * HW4 + s;
                    float4 x0 = __ldg(&Xg[(size_t)(bb + 0) * planeStride + off]);
                    float4 x1 = __ldg(&Xg[(size_t)(bb + 1) * planeStride + off]);
                    float4 x2 = __ldg(&Xg[(size_t)(bb + 2) * planeStride + off]);
                    float4 x3 = __ldg(&Xg[(size_t)(bb + 3) * planeStride + off]);
                    acc0.x += v * x0.x; acc0.y += v * x0.y; acc0.z += v * x0.z; acc0.w += v * x0.w;
                    acc1.x += v * x1.x; acc1.y += v * x1.y; acc1.z += v * x1.z; acc1.w += v * x1.w;
                    acc2.x += v * x2.x; acc2.y += v * x2.y; acc2.z += v * x2.z; acc2.w += v * x2.w;
                    acc3.x += v * x3.x; acc3.y += v * x3.y; acc3.z += v * x3.z; acc3.w += v * x3.w;
                }
                __stcs(&Og[(size_t)(bb + 0) * planeStride + s], acc0);
                __stcs(&Og[(size_t)(bb + 1) * planeStride + s], acc1);
                __stcs(&Og[(size_t)(bb + 2) * planeStride + s], acc2);
                __stcs(&Og[(size_t)(bb + 3) * planeStride + s], acc3);
            }
        }
    }
}

extern "C" void kernel_launch(void* const* d_in, const int* in_sizes, int n_in,
                              void* d_out, int out_size)
{
    const float4* X = (const float4*)d_in[0];   // x: 32*256*56*56 fp32
    const float4* W = (const float4*)d_in[1];   // conv_weights: 256*256*1*1 fp32
    float4* O = (float4*)d_out;

    dim3 grid(N_CH, NGROUPS);   // 1024 blocks: one per (o, 8-batch group)
    dim3 block(256);
    channel_pruner_kernel<<<grid, block>>>(X, W, O);
}

// round 4
// speedup vs baseline: 1.0514x; 1.0514x over previous
#include <cuda_runtime.h>
#include <cuda_bf16.h>

// ChannelPruner: out[b,o,h,w] = sum_c w[o,c] * x[b,c,h,w]
// x: (32, 256, 56, 56) fp32, w: (256, 256, 1, 1) fp32.
// Two-kernel generic sparse-row formulation (correct for ANY w):
//   K1: compact nonzeros of each w row into __device__ scratch (once).
//   K2: pure streaming, one block per (b,o) plane, NO barriers/scan in hot path.
// For the pruned-identity weight K2 degenerates to copy-or-zero.

#define N_CH   256
#define HW4    784          // 56*56/4 float4 per plane
#define NBATCH 32

// Scratch for compacted rows (device globals: allocation-free).
__device__ int   g_nnz[N_CH];
__device__ int   g_c[N_CH * N_CH];
__device__ float g_v[N_CH * N_CH];

// ---------------- K1: row compaction (deterministic order) ----------------
__global__ __launch_bounds__(64)
void compact_rows_kernel(const float4* __restrict__ W)
{
    const int o = blockIdx.x;      // row
    const int t = threadIdx.x;     // 64 threads, each owns 4 channels

    __shared__ int s_cnt[64];
    __shared__ int s_off[64];

    const float4 w4 = __ldg(&W[o * 64 + t]);
    const int cnt = (w4.x != 0.0f) + (w4.y != 0.0f) + (w4.z != 0.0f) + (w4.w != 0.0f);
    s_cnt[t] = cnt;
    __syncthreads();

    if (t == 0) {
        int run = 0;
        #pragma unroll
        for (int i = 0; i < 64; i++) { s_off[i] = run; run += s_cnt[i]; }
        g_nnz[o] = run;
    }
    __syncthreads();

    if (cnt > 0) {
        int p = o * N_CH + s_off[t];
        const int cbase = t * 4;
        if (w4.x != 0.0f) { g_c[p] = cbase + 0; g_v[p] = w4.x; p++; }
        if (w4.y != 0.0f) { g_c[p] = cbase + 1; g_v[p] = w4.y; p++; }
        if (w4.z != 0.0f) { g_c[p] = cbase + 2; g_v[p] = w4.z; p++; }
        if (w4.w != 0.0f) { g_c[p] = cbase + 3; g_v[p] = w4.w; p++; }
    }
}

// ---------------- K2: streaming apply (no barriers, no scan) ----------------
__global__ __launch_bounds__(256, 8)
void apply_kernel(const float4* __restrict__ X,
                  float4* __restrict__ O)
{
    const int o   = blockIdx.x;    // output channel
    const int b   = blockIdx.y;    // batch
    const int tid = threadIdx.x;   // 256 threads

    const int nnz = __ldg(&g_nnz[o]);          // uniform, L2-hit broadcast

    const size_t planeStride = (size_t)N_CH * HW4;
    const float4* __restrict__ Xb = X + (size_t)b * planeStride;
    float4* __restrict__ Ob = O + (size_t)b * planeStride + (size_t)o * HW4;

    if (nnz == 0) {
        const float4 z = make_float4(0.f, 0.f, 0.f, 0.f);
        Ob[tid]       = z;
        Ob[tid + 256] = z;
        Ob[tid + 512] = z;
        if (tid < HW4 - 768) Ob[tid + 768] = z;
    } else if (nnz == 1) {
        const float v = __ldg(&g_v[o * N_CH]);
        const int   c = __ldg(&g_c[o * N_CH]);
        const float4* __restrict__ Xc = Xb + (size_t)c * HW4;
        // 784 = 3*256 + 16: issue all loads before any store (MLP 3-4)
        float4 a0 = __ldg(&Xc[tid]);
        float4 a1 = __ldg(&Xc[tid + 256]);
        float4 a2 = __ldg(&Xc[tid + 512]);
        float4 a3;
        if (tid < HW4 - 768) a3 = __ldg(&Xc[tid + 768]);
        a0.x *= v; a0.y *= v; a0.z *= v; a0.w *= v;
        a1.x *= v; a1.y *= v; a1.z *= v; a1.w *= v;
        a2.x *= v; a2.y *= v; a2.z *= v; a2.w *= v;
        Ob[tid]       = a0;
        Ob[tid + 256] = a1;
        Ob[tid + 512] = a2;
        if (tid < HW4 - 768) {
            a3.x *= v; a3.y *= v; a3.z *= v; a3.w *= v;
            Ob[tid + 768] = a3;
        }
    } else {
        // generic sparse accumulation (values/indices are uniform L1/L2 hits)
        for (int s = tid; s < HW4; s += 256) {
            float4 acc = make_float4(0.f, 0.f, 0.f, 0.f);
            for (int k = 0; k < nnz; k++) {
                const float v = __ldg(&g_v[o * N_CH + k]);
                const int   c = __ldg(&g_c[o * N_CH + k]);
                const float4 xv = __ldg(&Xb[(size_t)c * HW4 + s]);
                acc.x += v * xv.x;
                acc.y += v * xv.y;
                acc.z += v * xv.z;
                acc.w += v * xv.w;
            }
            Ob[s] = acc;
        }
    }
}

extern "C" void kernel_launch(void* const* d_in, const int* in_sizes, int n_in,
                              void* d_out, int out_size)
{
    const float4* X = (const float4*)d_in[0];   // x: 32*256*56*56 fp32
    const float4* W = (const float4*)d_in[1];   // conv_weights: 256*256*1*1 fp32
    float4* O = (float4*)d_out;

    compact_rows_kernel<<<N_CH, 64>>>(W);                 // ~1-2 us
    dim3 grid(N_CH, NBATCH);                              // 8192 plane blocks
    apply_kernel<<<grid, 256>>>(X, O);
}

// round 6
// speedup vs baseline: 1.1147x; 1.0602x over previous
#include <cuda_runtime.h>
#include <cuda_bf16.h>

// ChannelPruner: out[b,o,h,w] = sum_c w[o,c] * x[b,c,h,w]
// x: (32, 256, 56, 56) fp32, w: (256, 256, 1, 1) fp32.
// Single fused kernel, generic sparse-row formulation (correct for ANY w):
// per-block compaction of row w[o,:] (costs ~0.5us total, cheaper than a
// second launch), then stream one (b,o) plane. Output uses streaming stores
// (__stcs) so x stays L2-resident -> reads are L2 hits, DRAM sees ~writes only.

#define N_CH   256
#define HW4    784          // 56*56/4 float4 per plane
#define NBATCH 32

__global__ __launch_bounds__(256, 8)
void channel_pruner_kernel(const float4* __restrict__ X,
                           const float4* __restrict__ W,   // row o = W[o*64 .. o*64+63]
                           float4* __restrict__ O)
{
    const int o   = blockIdx.x;    // output channel
    const int b   = blockIdx.y;    // batch
    const int tid = threadIdx.x;   // 256 threads

    __shared__ int   s_cnt[64];
    __shared__ int   s_off[64];
    __shared__ int   s_nnz;
    __shared__ int   s_c[N_CH];
    __shared__ float s_v[N_CH];

    // --- Phase 1: cooperative scan of w row o (64 float4 = 256 floats) ---
    float4 w4;
    int myCnt = 0;
    if (tid < 64) {
        w4 = __ldg(&W[o * 64 + tid]);
        myCnt = (w4.x != 0.0f) + (w4.y != 0.0f) + (w4.z != 0.0f) + (w4.w != 0.0f);
        s_cnt[tid] = myCnt;
    }
    __syncthreads();

    if (tid == 0) {
        int run = 0;
        #pragma unroll
        for (int i = 0; i < 64; i++) { s_off[i] = run; run += s_cnt[i]; }
        s_nnz = run;
    }
    __syncthreads();

    if (tid < 64 && myCnt > 0) {
        int p = s_off[tid];
        const int cbase = tid * 4;
        if (w4.x != 0.0f) { s_c[p] = cbase + 0; s_v[p] = w4.x; p++; }
        if (w4.y != 0.0f) { s_c[p] = cbase + 1; s_v[p] = w4.y; p++; }
        if (w4.z != 0.0f) { s_c[p] = cbase + 2; s_v[p] = w4.z; p++; }
        if (w4.w != 0.0f) { s_c[p] = cbase + 3; s_v[p] = w4.w; p++; }
    }
    __syncthreads();

    const int nnz = s_nnz;
    const size_t planeStride = (size_t)N_CH * HW4;
    const float4* __restrict__ Xb = X + (size_t)b * planeStride;
    float4* __restrict__ Ob = O + (size_t)b * planeStride + (size_t)o * HW4;

    // --- Phase 2: stream the plane with streaming (evict-first) stores ---
    if (nnz == 0) {
        const float4 z = make_float4(0.f, 0.f, 0.f, 0.f);
        __stcs(&Ob[tid],       z);
        __stcs(&Ob[tid + 256], z);
        __stcs(&Ob[tid + 512], z);
        if (tid < HW4 - 768) __stcs(&Ob[tid + 768], z);
    } else if (nnz == 1) {
        const float v = s_v[0];
        const float4* __restrict__ Xc = Xb + (size_t)s_c[0] * HW4;
        // 784 = 3*256 + 16: all loads issued before any store (MLP 3-4)
        float4 a0 = __ldg(&Xc[tid]);
        float4 a1 = __ldg(&Xc[tid + 256]);
        float4 a2 = __ldg(&Xc[tid + 512]);
        float4 a3;
        if (tid < HW4 - 768) a3 = __ldg(&Xc[tid + 768]);
        a0.x *= v; a0.y *= v; a0.z *= v; a0.w *= v;
        a1.x *= v; a1.y *= v; a1.z *= v; a1.w *= v;
        a2.x *= v; a2.y *= v; a2.z *= v; a2.w *= v;
        __stcs(&Ob[tid],       a0);
        __stcs(&Ob[tid + 256], a1);
        __stcs(&Ob[tid + 512], a2);
        if (tid < HW4 - 768) {
            a3.x *= v; a3.y *= v; a3.z *= v; a3.w *= v;
            __stcs(&Ob[tid + 768], a3);
        }
    } else {
        // generic sparse accumulation (indices/values are smem hits)
        for (int s = tid; s < HW4; s += 256) {
            float4 acc = make_float4(0.f, 0.f, 0.f, 0.f);
            for (int k = 0; k < nnz; k++) {
                const float v = s_v[k];
                const float4 xv = __ldg(&Xb[(size_t)s_c[k] * HW4 + s]);
                acc.x += v * xv.x;
                acc.y += v * xv.y;
                acc.z += v * xv.z;
                acc.w += v * xv.w;
            }
            __stcs(&Ob[s], acc);
        }
    }
}

extern "C" void kernel_launch(void* const* d_in, const int* in_sizes, int n_in,
                              void* d_out, int out_size)
{
    const float4* X = (const float4*)d_in[0];   // x: 32*256*56*56 fp32
    const float4* W = (const float4*)d_in[1];   // conv_weights: 256*256*1*1 fp32
    float4* O = (float4*)d_out;

    dim3 grid(N_CH, NBATCH);    // 8192 blocks: one per (b, o) plane
    channel_pruner_kernel<<<grid, 256>>>(X, W, O);
}

// round 8
// speedup vs baseline: 1.1222x; 1.0067x over previous
#include <cuda_runtime.h>
#include <cuda_bf16.h>

// ChannelPruner: out[b,o,h,w] = sum_c w[o,c] * x[b,c,h,w]
// x: (32, 256, 56, 56) fp32, w: (256, 256, 1, 1) fp32.
// Fused generic sparse-row kernel (correct for ANY w): per-block compaction
// of row w[o,:], then stream one (b,o) plane. Output uses write-through
// stores (__stwt): no L2 write-allocate -> x stays fully L2-resident,
// DRAM sees (almost) only the mandatory 103 MB write stream.

#define N_CH   256
#define HW4    784          // 56*56/4 float4 per plane
#define NBATCH 32

__global__ __launch_bounds__(256, 8)
void channel_pruner_kernel(const float4* __restrict__ X,
                           const float4* __restrict__ W,   // row o = W[o*64 .. o*64+63]
                           float4* __restrict__ O)
{
    const int o   = blockIdx.x;    // output channel
    const int b   = blockIdx.y;    // batch
    const int tid = threadIdx.x;   // 256 threads

    __shared__ int   s_cnt[64];
    __shared__ int   s_off[64];
    __shared__ int   s_nnz;
    __shared__ int   s_c[N_CH];
    __shared__ float s_v[N_CH];

    // --- Phase 1: cooperative scan of w row o (64 float4 = 256 floats) ---
    float4 w4;
    int myCnt = 0;
    if (tid < 64) {
        w4 = __ldg(&W[o * 64 + tid]);
        myCnt = (w4.x != 0.0f) + (w4.y != 0.0f) + (w4.z != 0.0f) + (w4.w != 0.0f);
        s_cnt[tid] = myCnt;
    }
    __syncthreads();

    if (tid == 0) {
        int run = 0;
        #pragma unroll
        for (int i = 0; i < 64; i++) { s_off[i] = run; run += s_cnt[i]; }
        s_nnz = run;
    }
    __syncthreads();

    if (tid < 64 && myCnt > 0) {
        int p = s_off[tid];
        const int cbase = tid * 4;
        if (w4.x != 0.0f) { s_c[p] = cbase + 0; s_v[p] = w4.x; p++; }
        if (w4.y != 0.0f) { s_c[p] = cbase + 1; s_v[p] = w4.y; p++; }
        if (w4.z != 0.0f) { s_c[p] = cbase + 2; s_v[p] = w4.z; p++; }
        if (w4.w != 0.0f) { s_c[p] = cbase + 3; s_v[p] = w4.w; p++; }
    }
    __syncthreads();

    const int nnz = s_nnz;
    const size_t planeStride = (size_t)N_CH * HW4;
    const float4* __restrict__ Xb = X + (size_t)b * planeStride;
    float4* __restrict__ Ob = O + (size_t)b * planeStride + (size_t)o * HW4;

    // --- Phase 2: stream the plane with write-through (no-L2-alloc) stores ---
    if (nnz == 0) {
        const float4 z = make_float4(0.f, 0.f, 0.f, 0.f);
        __stwt(&Ob[tid],       z);
        __stwt(&Ob[tid + 256], z);
        __stwt(&Ob[tid + 512], z);
        if (tid < HW4 - 768) __stwt(&Ob[tid + 768], z);
    } else if (nnz == 1) {
        const float v = s_v[0];
        const float4* __restrict__ Xc = Xb + (size_t)s_c[0] * HW4;
        // 784 = 3*256 + 16: all loads issued before any store (MLP 3-4)
        float4 a0 = __ldg(&Xc[tid]);
        float4 a1 = __ldg(&Xc[tid + 256]);
        float4 a2 = __ldg(&Xc[tid + 512]);
        float4 a3;
        if (tid < HW4 - 768) a3 = __ldg(&Xc[tid + 768]);
        a0.x *= v; a0.y *= v; a0.z *= v; a0.w *= v;
        a1.x *= v; a1.y *= v; a1.z *= v; a1.w *= v;
        a2.x *= v; a2.y *= v; a2.z *= v; a2.w *= v;
        __stwt(&Ob[tid],       a0);
        __stwt(&Ob[tid + 256], a1);
        __stwt(&Ob[tid + 512], a2);
        if (tid < HW4 - 768) {
            a3.x *= v; a3.y *= v; a3.z *= v; a3.w *= v;
            __stwt(&Ob[tid + 768], a3);
        }
    } else {
        // generic sparse accumulation (indices/values are smem hits)
        for (int s = tid; s < HW4; s += 256) {
            float4 acc = make_float4(0.f, 0.f, 0.f, 0.f);
            for (int k = 0; k < nnz; k++) {
                const float v = s_v[k];
                const float4 xv = __ldg(&Xb[(size_t)s_c[k] * HW4 + s]);
                acc.x += v * xv.x;
                acc.y += v * xv.y;
                acc.z += v * xv.z;
                acc.w += v * xv.w;
            }
            __stwt(&Ob[s], acc);
        }
    }
}

extern "C" void kernel_launch(void* const* d_in, const int* in_sizes, int n_in,
                              void* d_out, int out_size)
{
    const float4* X = (const float4*)d_in[0];   // x: 32*256*56*56 fp32
    const float4* W = (const float4*)d_in[1];   // conv_weights: 256*256*1*1 fp32
    float4* O = (float4*)d_out;

    dim3 grid(N_CH, NBATCH);    // 8192 blocks: one per (b, o) plane
    channel_pruner_kernel<<<grid, 256>>>(X, W, O);
}